// round 4
// baseline (speedup 1.0000x reference)
#include <cuda_runtime.h>
#include <cstdint>
#include <cstddef>

// Problem dims (fixed by the dataset)
#define Ltok 768
#define Ddim 1024
#define DPd  128
#define Pp   64     // DP/2
#define Hd   128
#define NBd  64

// ---------------- scratch (device globals; no allocation allowed) -------------
__device__ float g_q [Ltok * Pp];
__device__ float g_k [Ltok * Pp];
__device__ float g_Dq[Ltok * Hd];   // Dq'[j,h] = sum_p W1[h,64+p] q[j,p] + b1[h]
__device__ float g_Dk[Ltok * Hd];   // Dk [i,h] = sum_p W1[h,64+p] k[i,p]
__device__ float g_part[8 * Ltok * DPd];  // split-K partials for down-proj

// ---------------- packed f32x2 helpers (2x FFMA throughput on sm_100) ---------
__device__ __forceinline__ unsigned long long pack2(float lo, float hi) {
    unsigned long long r;
    asm("mov.b64 %0, {%1, %2};" : "=l"(r) : "f"(lo), "f"(hi));
    return r;
}
__device__ __forceinline__ void unpack2(unsigned long long v, float& lo, float& hi) {
    asm("mov.b64 {%0, %1}, %2;" : "=f"(lo), "=f"(hi) : "l"(v));
}
__device__ __forceinline__ void ffma2(unsigned long long& acc,
                                      unsigned long long a, unsigned long long b) {
    asm("fma.rn.f32x2 %0, %1, %2, %0;" : "+l"(acc) : "l"(a), "l"(b));
}

// =============================================================================
// Kernel 1: down-projection partials.  xd = x @ W_down^T  (bias added in reduce)
// Split-K: grid (12, 8); block handles 64 rows x 128 cols over K range of 128.
// =============================================================================
__global__ __launch_bounds__(256) void k_down(const float* __restrict__ x,
                                              const float* __restrict__ Wd) {
    __shared__ float xs[64][33];    // [m][k] pad 33
    __shared__ float ws[32][132];   // [k][p] pad 132 (16B-aligned rows)
    const int t  = threadIdx.x;
    const int tx = t & 15, ty = t >> 4;
    const int m0 = blockIdx.x * 64;
    const int kb = blockIdx.y;      // 0..7

    unsigned long long acc[4][4];
#pragma unroll
    for (int u = 0; u < 4; u++)
#pragma unroll
        for (int v = 0; v < 4; v++) acc[u][v] = 0ull;

    const int dbeg = kb * 128;
    for (int d0 = dbeg; d0 < dbeg + 128; d0 += 32) {
        __syncthreads();
        for (int idx = t; idx < 64 * 32; idx += 256) {
            int kk = idx & 31, mm = idx >> 5;
            xs[mm][kk] = x[(size_t)(m0 + mm) * Ddim + d0 + kk];
        }
        for (int idx = t; idx < 32 * 128; idx += 256) {
            int kk = idx & 31, p = idx >> 5;
            ws[kk][p] = Wd[(size_t)p * Ddim + d0 + kk];
        }
        __syncthreads();
#pragma unroll 8
        for (int kk = 0; kk < 32; kk++) {
            ulonglong2 b0 = *(const ulonglong2*)&ws[kk][tx * 8];
            ulonglong2 b1 = *(const ulonglong2*)&ws[kk][tx * 8 + 4];
#pragma unroll
            for (int u = 0; u < 4; u++) {
                float av = xs[ty * 4 + u][kk];
                unsigned long long ad = pack2(av, av);
                ffma2(acc[u][0], ad, b0.x);
                ffma2(acc[u][1], ad, b0.y);
                ffma2(acc[u][2], ad, b1.x);
                ffma2(acc[u][3], ad, b1.y);
            }
        }
    }
    float* part = &g_part[(size_t)kb * Ltok * DPd];
#pragma unroll
    for (int u = 0; u < 4; u++) {
        int m = m0 + ty * 4 + u;
#pragma unroll
        for (int vp = 0; vp < 4; vp++) {
            float lo, hi;
            unpack2(acc[u][vp], lo, hi);
            part[m * DPd + tx * 8 + vp * 2]     = lo;
            part[m * DPd + tx * 8 + vp * 2 + 1] = hi;
        }
    }
}

// =============================================================================
// Kernel 2: reduce split-K partials + bias, split into q / k halves.
// =============================================================================
__global__ __launch_bounds__(256) void k_reduce(const float* __restrict__ bd) {
    int idx = blockIdx.x * 256 + threadIdx.x;  // < 768*128
    int p = idx & 127, m = idx >> 7;
    float s = bd[p];
#pragma unroll
    for (int r = 0; r < 8; r++) s += g_part[(size_t)r * Ltok * DPd + idx];
    if (p < Pp) g_q[m * Pp + p] = s;
    else        g_k[m * Pp + (p - Pp)] = s;
}

// =============================================================================
// Kernel 3: Dq'[l,h] = sum_p W1[h,64+p] q[l,p] + b1[h];  Dk[l,h] likewise (no b1)
// =============================================================================
__global__ __launch_bounds__(128) void k_dqdk(const float* __restrict__ W1,
                                              const float* __restrict__ b1) {
    const int l = blockIdx.x, h = threadIdx.x;
    __shared__ float qs[64], ks[64];
    if (h < 64) qs[h] = g_q[l * 64 + h];
    else        ks[h - 64] = g_k[l * 64 + (h - 64)];
    __syncthreads();
    float aq = b1[h], ak = 0.f;
    const float4* w4 = (const float4*)&W1[(size_t)h * DPd + Pp];
#pragma unroll
    for (int p4 = 0; p4 < 16; p4++) {
        float4 w = w4[p4];
        int b = p4 * 4;
        aq = fmaf(w.x, qs[b + 0], aq); ak = fmaf(w.x, ks[b + 0], ak);
        aq = fmaf(w.y, qs[b + 1], aq); ak = fmaf(w.y, ks[b + 1], ak);
        aq = fmaf(w.z, qs[b + 2], aq); ak = fmaf(w.z, ks[b + 2], ak);
        aq = fmaf(w.w, qs[b + 3], aq); ak = fmaf(w.w, ks[b + 3], ak);
    }
    g_Dq[l * Hd + h] = aq;
    g_Dk[l * Hd + h] = ak;
}

// =============================================================================
// Kernel 4 (main, fused): per CTA 8 i x 16 j = 128 pairs.
//   GEMM1 (128x128 x K=64) -> +Dq-Dk -> exact GELU -> LN(128) -> GEMM2 (x64) -> out
// Dynamic smem layout (floats):
//   stage 1: hin[128*65] @0 ; w1s[64*132] @8320            (end 16768)
//   stage 2: y  [128*130] @0 ; w2s[128*68] @16640          (end 25344)
//   persistent smalls @25344: gln[128], bln[128], b2s[64]  (total 25664 floats)
// =============================================================================
#define SM_W1S   (128 * 65)
#define SM_W2S   (128 * 130)
#define SM_SMALL (SM_W2S + 128 * 68)
#define SMEM_FLOATS (SM_SMALL + 320)
#define SMEM_BYTES  (SMEM_FLOATS * 4)

__global__ __launch_bounds__(256, 2) void k_main(const float* __restrict__ W1,
                                                 const float* __restrict__ ln_g,
                                                 const float* __restrict__ ln_b,
                                                 const float* __restrict__ W2,
                                                 const float* __restrict__ b2,
                                                 float* __restrict__ out) {
    extern __shared__ float sm[];
    const int t  = threadIdx.x;
    const int tx = t & 15, ty = t >> 4;
    const int j0 = blockIdx.x * 16;   // 48 tiles
    const int i0 = blockIdx.y * 8;    // 96 tiles

    float* hin = sm;                 // [pair][p], pad 65
    float* w1s = sm + SM_W1S;        // [p][h],   pad 132
    float* gln = sm + SM_SMALL;
    float* bln = gln + 128;
    float* b2s = bln + 128;

    // --- stage-1 loads ---
    for (int idx = t; idx < 128 * 64; idx += 256) {
        int pair = idx >> 6, p = idx & 63;
        int jj = pair & 15, ii = pair >> 4;
        hin[pair * 65 + p] = g_q[(j0 + jj) * 64 + p] * g_k[(i0 + ii) * 64 + p];
    }
    for (int idx = t; idx < 64 * 128; idx += 256) {
        int p = idx & 63, h = idx >> 6;
        w1s[p * 132 + h] = W1[(size_t)h * DPd + p];   // prod half of W1
    }
    if (t < 128) gln[t] = ln_g[t];
    else         bln[t - 128] = ln_b[t - 128];
    if (t < 64)  b2s[t] = b2[t];
    __syncthreads();

    // --- GEMM1: acc[pair][h], 8x8 per thread, packed f32x2 ---
    unsigned long long acc[8][4];
#pragma unroll
    for (int u = 0; u < 8; u++)
#pragma unroll
        for (int v = 0; v < 4; v++) acc[u][v] = 0ull;

#pragma unroll 2
    for (int k = 0; k < 64; k++) {
        ulonglong2 b0 = *(const ulonglong2*)&w1s[k * 132 + tx * 8];
        ulonglong2 b1 = *(const ulonglong2*)&w1s[k * 132 + tx * 8 + 4];
#pragma unroll
        for (int u = 0; u < 8; u++) {
            float av = hin[(ty * 8 + u) * 65 + k];
            unsigned long long ad = pack2(av, av);
            ffma2(acc[u][0], ad, b0.x);
            ffma2(acc[u][1], ad, b0.y);
            ffma2(acc[u][2], ad, b1.x);
            ffma2(acc[u][3], ad, b1.y);
        }
    }
    __syncthreads();   // all reads of hin/w1s done; region is reused as y

    // --- epilogue 1: + Dq - Dk, exact GELU, stage into y ---
    float* y   = sm;                 // [pair][h], pad 130
    float* w2s = sm + SM_W2S;        // [h][n],   pad 68
#pragma unroll
    for (int u = 0; u < 8; u++) {
        int pair = ty * 8 + u;
        int jj = pair & 15, ii = pair >> 4;
        const float* dq = &g_Dq[(j0 + jj) * Hd + tx * 8];
        const float* dk = &g_Dk[(i0 + ii) * Hd + tx * 8];
        float* yr = &y[pair * 130 + tx * 8];
#pragma unroll
        for (int vp = 0; vp < 4; vp++) {
            float lo, hi;
            unpack2(acc[u][vp], lo, hi);
            float x0 = lo + dq[vp * 2]     - dk[vp * 2];
            float x1 = hi + dq[vp * 2 + 1] - dk[vp * 2 + 1];
            yr[vp * 2]     = 0.5f * x0 * (1.0f + erff(x0 * 0.70710678118654752f));
            yr[vp * 2 + 1] = 0.5f * x1 * (1.0f + erff(x1 * 0.70710678118654752f));
        }
    }
    // load W2 transposed while y is being staged (disjoint smem region)
    for (int idx = t; idx < 64 * 128; idx += 256) {
        int h = idx & 127, n = idx >> 7;
        w2s[h * 68 + n] = W2[(size_t)n * Hd + h];
    }
    __syncthreads();

    // --- LayerNorm over H=128 (2 threads per pair, shuffle combine) ---
    {
        int pair = t >> 1, half = t & 1;
        float* row = &y[pair * 130 + half * 64];
        float s = 0.f, s2 = 0.f;
#pragma unroll
        for (int c = 0; c < 64; c++) { float v = row[c]; s += v; s2 += v * v; }
        s  += __shfl_xor_sync(0xffffffffu, s, 1);
        s2 += __shfl_xor_sync(0xffffffffu, s2, 1);
        float mu   = s * (1.0f / 128.0f);
        float var  = s2 * (1.0f / 128.0f) - mu * mu;
        float rstd = rsqrtf(var + 1e-5f);
#pragma unroll
        for (int c = 0; c < 64; c++) {
            int h = half * 64 + c;
            row[c] = (row[c] - mu) * rstd * gln[h] + bln[h];
        }
    }
    __syncthreads();

    // --- GEMM2: out[pair][n], 8x4 per thread, K=128 ---
    unsigned long long acc2[8][2];
#pragma unroll
    for (int u = 0; u < 8; u++) { acc2[u][0] = 0ull; acc2[u][1] = 0ull; }

#pragma unroll 2
    for (int k = 0; k < 128; k++) {
        ulonglong2 bv = *(const ulonglong2*)&w2s[k * 68 + tx * 4];
#pragma unroll
        for (int u = 0; u < 8; u++) {
            float av = y[(ty * 8 + u) * 130 + k];
            unsigned long long ad = pack2(av, av);
            ffma2(acc2[u][0], ad, bv.x);
            ffma2(acc2[u][1], ad, bv.y);
        }
    }

#pragma unroll
    for (int u = 0; u < 8; u++) {
        int pair = ty * 8 + u;
        int jj = pair & 15, ii = pair >> 4;
        float4 o;
        unpack2(acc2[u][0], o.x, o.y);
        unpack2(acc2[u][1], o.z, o.w);
        o.x += b2s[tx * 4 + 0];
        o.y += b2s[tx * 4 + 1];
        o.z += b2s[tx * 4 + 2];
        o.w += b2s[tx * 4 + 3];
        *(float4*)&out[((size_t)(i0 + ii) * Ltok + (j0 + jj)) * NBd + tx * 4] = o;
    }
}

// =============================================================================
extern "C" void kernel_launch(void* const* d_in, const int* in_sizes, int n_in,
                              void* d_out, int out_size) {
    const float* x   = (const float*)d_in[0];
    const float* Wd  = (const float*)d_in[1];
    const float* bd  = (const float*)d_in[2];
    const float* W1  = (const float*)d_in[3];
    const float* b1  = (const float*)d_in[4];
    const float* lng = (const float*)d_in[5];
    const float* lnb = (const float*)d_in[6];
    const float* W2  = (const float*)d_in[7];
    const float* b2  = (const float*)d_in[8];
    float* out = (float*)d_out;

    cudaFuncSetAttribute(k_main, cudaFuncAttributeMaxDynamicSharedMemorySize, SMEM_BYTES);

    k_down  <<<dim3(12, 8), 256>>>(x, Wd);
    k_reduce<<<384, 256>>>(bd);
    k_dqdk  <<<Ltok, 128>>>(W1, b1);
    k_main  <<<dim3(48, 96), 256, SMEM_BYTES>>>(W1, lng, lnb, W2, b2, out);
}

// round 6
// speedup vs baseline: 1.1394x; 1.1394x over previous
#include <cuda_runtime.h>
#include <cstdint>
#include <cstddef>

// Problem dims (fixed by the dataset)
#define Ltok 768
#define Ddim 1024
#define DPd  128
#define Pp   64     // DP/2
#define Hd   128
#define NBd  64

// ---------------- scratch (device globals; no allocation allowed) -------------
__device__ float g_q [Ltok * Pp];
__device__ float g_k [Ltok * Pp];
__device__ float g_Dq[Ltok * Hd];   // Dq'[j,h] = sum_p W1[h,64+p] q[j,p] + b1[h]
__device__ float g_Dk[Ltok * Hd];   // Dk [i,h] = sum_p W1[h,64+p] k[i,p]
__device__ float g_part[8 * Ltok * DPd];  // split-K partials for down-proj

// ---------------- packed f32x2 helpers (2x FFMA throughput on sm_100) ---------
__device__ __forceinline__ unsigned long long pack2(float lo, float hi) {
    unsigned long long r;
    asm("mov.b64 %0, {%1, %2};" : "=l"(r) : "f"(lo), "f"(hi));
    return r;
}
__device__ __forceinline__ void unpack2(unsigned long long v, float& lo, float& hi) {
    asm("mov.b64 {%0, %1}, %2;" : "=f"(lo), "=f"(hi) : "l"(v));
}
__device__ __forceinline__ void ffma2(unsigned long long& acc,
                                      unsigned long long a, unsigned long long b) {
    asm("fma.rn.f32x2 %0, %1, %2, %0;" : "+l"(acc) : "l"(a), "l"(b));
}

// =============================================================================
// Kernel 1: down-projection partials.  xd = x @ W_down^T  (bias added in reduce)
// Split-K: grid (12, 8); block handles 64 rows x 128 cols over K range of 128.
// =============================================================================
__global__ __launch_bounds__(256) void k_down(const float* __restrict__ x,
                                              const float* __restrict__ Wd) {
    __shared__ float xs[64][36];    // [m][k] pad 36 (16B-aligned rows)
    __shared__ float ws[32][132];   // [k][p] pad 132 (16B-aligned rows)
    const int t  = threadIdx.x;
    const int tx = t & 15, ty = t >> 4;
    const int m0 = blockIdx.x * 64;
    const int kb = blockIdx.y;      // 0..7

    unsigned long long acc[4][4];
#pragma unroll
    for (int u = 0; u < 4; u++)
#pragma unroll
        for (int v = 0; v < 4; v++) acc[u][v] = 0ull;

    const int dbeg = kb * 128;
    for (int d0 = dbeg; d0 < dbeg + 128; d0 += 32) {
        __syncthreads();
        for (int idx = t; idx < 64 * 32; idx += 256) {
            int kk = idx & 31, mm = idx >> 5;
            xs[mm][kk] = x[(size_t)(m0 + mm) * Ddim + d0 + kk];
        }
        for (int idx = t; idx < 32 * 128; idx += 256) {
            int kk = idx & 31, p = idx >> 5;
            ws[kk][p] = Wd[(size_t)p * Ddim + d0 + kk];
        }
        __syncthreads();
#pragma unroll
        for (int k = 0; k < 32; k += 4) {
            float4 a4[4];
#pragma unroll
            for (int u = 0; u < 4; u++)
                a4[u] = *(const float4*)&xs[ty * 4 + u][k];
#pragma unroll
            for (int kk = 0; kk < 4; kk++) {
                const float* wrow = &ws[k + kk][tx * 8];
                ulonglong2 b0 = *(const ulonglong2*)(wrow);
                ulonglong2 b1 = *(const ulonglong2*)(wrow + 4);
#pragma unroll
                for (int u = 0; u < 4; u++) {
                    float av = (&a4[u].x)[kk];
                    unsigned long long ad = pack2(av, av);
                    ffma2(acc[u][0], ad, b0.x);
                    ffma2(acc[u][1], ad, b0.y);
                    ffma2(acc[u][2], ad, b1.x);
                    ffma2(acc[u][3], ad, b1.y);
                }
            }
        }
    }
    float* part = &g_part[(size_t)kb * Ltok * DPd];
#pragma unroll
    for (int u = 0; u < 4; u++) {
        int m = m0 + ty * 4 + u;
#pragma unroll
        for (int vp = 0; vp < 4; vp++) {
            float lo, hi;
            unpack2(acc[u][vp], lo, hi);
            part[m * DPd + tx * 8 + vp * 2]     = lo;
            part[m * DPd + tx * 8 + vp * 2 + 1] = hi;
        }
    }
}

// =============================================================================
// Kernel 2: reduce split-K partials + bias, split into q / k halves.
// =============================================================================
__global__ __launch_bounds__(256) void k_reduce(const float* __restrict__ bd) {
    int idx = blockIdx.x * 256 + threadIdx.x;  // < 768*128
    int p = idx & 127, m = idx >> 7;
    float s = bd[p];
#pragma unroll
    for (int r = 0; r < 8; r++) s += g_part[(size_t)r * Ltok * DPd + idx];
    if (p < Pp) g_q[m * Pp + p] = s;
    else        g_k[m * Pp + (p - Pp)] = s;
}

// =============================================================================
// Kernel 3: Dq'[l,h] = sum_p W1[h,64+p] q[l,p] + b1[h];  Dk[l,h] likewise (no b1)
// =============================================================================
__global__ __launch_bounds__(128) void k_dqdk(const float* __restrict__ W1,
                                              const float* __restrict__ b1) {
    const int l = blockIdx.x, h = threadIdx.x;
    __shared__ float qs[64], ks[64];
    if (h < 64) qs[h] = g_q[l * 64 + h];
    else        ks[h - 64] = g_k[l * 64 + (h - 64)];
    __syncthreads();
    float aq = b1[h], ak = 0.f;
    const float4* w4 = (const float4*)&W1[(size_t)h * DPd + Pp];
#pragma unroll
    for (int p4 = 0; p4 < 16; p4++) {
        float4 w = w4[p4];
        int b = p4 * 4;
        aq = fmaf(w.x, qs[b + 0], aq); ak = fmaf(w.x, ks[b + 0], ak);
        aq = fmaf(w.y, qs[b + 1], aq); ak = fmaf(w.y, ks[b + 1], ak);
        aq = fmaf(w.z, qs[b + 2], aq); ak = fmaf(w.z, ks[b + 2], ak);
        aq = fmaf(w.w, qs[b + 3], aq); ak = fmaf(w.w, ks[b + 3], ak);
    }
    g_Dq[l * Hd + h] = aq;
    g_Dk[l * Hd + h] = ak;
}

// =============================================================================
// Kernel 4 (main, fused): per CTA 8 i x 16 j = 128 pairs.
//   GEMM1 (128x128 x K=64) -> +Dq-Dk -> exact GELU -> LN(128) -> GEMM2 (x64) -> out
// Dynamic smem layout (floats):
//   stage 1: hin[128*68] @0 ; w1s[64*132] @8704             (end 17152)
//   stage 2: y  [128*132] @0 ; w2s[128*68] @16896           (end 25600)
//   persistent smalls @25600: gln[128], bln[128], b2s[64]   (total 25920 floats)
// All row strides are multiples of 4 floats so rows are 16B-aligned for LDS.128.
// =============================================================================
#define PAD_HIN  68
#define PAD_W1S  132
#define PAD_Y    132
#define PAD_W2S  68
#define SM_W1S   (128 * PAD_HIN)
#define SM_W2S   (128 * PAD_Y)
#define SM_SMALL (SM_W2S + 128 * PAD_W2S)
#define SMEM_FLOATS (SM_SMALL + 320)
#define SMEM_BYTES  (SMEM_FLOATS * 4)

__global__ __launch_bounds__(256, 2) void k_main(const float* __restrict__ W1,
                                                 const float* __restrict__ ln_g,
                                                 const float* __restrict__ ln_b,
                                                 const float* __restrict__ W2,
                                                 const float* __restrict__ b2,
                                                 float* __restrict__ out) {
    extern __shared__ float sm[];
    const int t  = threadIdx.x;
    const int tx = t & 15, ty = t >> 4;
    const int j0 = blockIdx.x * 16;   // 48 tiles
    const int i0 = blockIdx.y * 8;    // 96 tiles

    float* hin = sm;                 // [pair][p], stride PAD_HIN
    float* w1s = sm + SM_W1S;        // [p][h],   stride PAD_W1S
    float* gln = sm + SM_SMALL;
    float* bln = gln + 128;
    float* b2s = bln + 128;

    // --- stage-1 loads (vectorized hin fill: q*k per pair) ---
    for (int idx = t; idx < 128 * 16; idx += 256) {
        int pair = idx >> 4, p4 = idx & 15;
        int jj = pair & 15, ii = pair >> 4;
        float4 qv = *(const float4*)&g_q[(j0 + jj) * 64 + p4 * 4];
        float4 kv = *(const float4*)&g_k[(i0 + ii) * 64 + p4 * 4];
        float4 hv;
        hv.x = qv.x * kv.x; hv.y = qv.y * kv.y;
        hv.z = qv.z * kv.z; hv.w = qv.w * kv.w;
        *(float4*)&hin[pair * PAD_HIN + p4 * 4] = hv;
    }
    for (int idx = t; idx < 64 * 128; idx += 256) {
        int p = idx & 63, h = idx >> 6;
        w1s[p * PAD_W1S + h] = W1[(size_t)h * DPd + p];   // prod half of W1
    }
    if (t < 128) gln[t] = ln_g[t];
    else         bln[t - 128] = ln_b[t - 128];
    if (t < 64)  b2s[t] = b2[t];
    __syncthreads();

    // --- GEMM1: acc[pair][h], 8x8 per thread, packed f32x2, k blocked by 4 ---
    unsigned long long acc[8][4];
#pragma unroll
    for (int u = 0; u < 8; u++)
#pragma unroll
        for (int v = 0; v < 4; v++) acc[u][v] = 0ull;

    for (int k = 0; k < 64; k += 4) {
        float4 a4[8];
#pragma unroll
        for (int u = 0; u < 8; u++)
            a4[u] = *(const float4*)&hin[(ty * 8 + u) * PAD_HIN + k];
#pragma unroll
        for (int kk = 0; kk < 4; kk++) {
            const float* wrow = &w1s[(k + kk) * PAD_W1S + tx * 8];
            ulonglong2 b0 = *(const ulonglong2*)(wrow);
            ulonglong2 b1 = *(const ulonglong2*)(wrow + 4);
#pragma unroll
            for (int u = 0; u < 8; u++) {
                float av = (&a4[u].x)[kk];
                unsigned long long ad = pack2(av, av);
                ffma2(acc[u][0], ad, b0.x);
                ffma2(acc[u][1], ad, b0.y);
                ffma2(acc[u][2], ad, b1.x);
                ffma2(acc[u][3], ad, b1.y);
            }
        }
    }
    __syncthreads();   // all reads of hin/w1s done; region is reused as y

    // --- epilogue 1: + Dq - Dk, exact GELU, stage into y ---
    float* y   = sm;                 // [pair][h], stride PAD_Y
    float* w2s = sm + SM_W2S;        // [h][n],   stride PAD_W2S
#pragma unroll
    for (int u = 0; u < 8; u++) {
        int pair = ty * 8 + u;
        int jj = pair & 15, ii = pair >> 4;
        const float4* dq4 = (const float4*)&g_Dq[(j0 + jj) * Hd + tx * 8];
        const float4* dk4 = (const float4*)&g_Dk[(i0 + ii) * Hd + tx * 8];
        float4 dq0 = dq4[0], dq1 = dq4[1];
        float4 dk0 = dk4[0], dk1 = dk4[1];
        float d[8];
        d[0] = dq0.x - dk0.x; d[1] = dq0.y - dk0.y;
        d[2] = dq0.z - dk0.z; d[3] = dq0.w - dk0.w;
        d[4] = dq1.x - dk1.x; d[5] = dq1.y - dk1.y;
        d[6] = dq1.z - dk1.z; d[7] = dq1.w - dk1.w;
        float* yr = &y[pair * PAD_Y + tx * 8];
#pragma unroll
        for (int vp = 0; vp < 4; vp++) {
            float lo, hi;
            unpack2(acc[u][vp], lo, hi);
            float x0 = lo + d[vp * 2];
            float x1 = hi + d[vp * 2 + 1];
            yr[vp * 2]     = 0.5f * x0 * (1.0f + erff(x0 * 0.70710678118654752f));
            yr[vp * 2 + 1] = 0.5f * x1 * (1.0f + erff(x1 * 0.70710678118654752f));
        }
    }
    // load W2 transposed while y is being staged (disjoint smem region)
    for (int idx = t; idx < 64 * 128; idx += 256) {
        int h = idx & 127, n = idx >> 7;
        w2s[h * PAD_W2S + n] = W2[(size_t)n * Hd + h];
    }
    __syncthreads();

    // --- LayerNorm over H=128 (2 threads per pair, shuffle combine, f4 I/O) ---
    {
        int pair = t >> 1, half = t & 1;
        float4* row4 = (float4*)&y[pair * PAD_Y + half * 64];
        const float4* g4 = (const float4*)&gln[half * 64];
        const float4* bb4 = (const float4*)&bln[half * 64];
        float s = 0.f, s2 = 0.f;
#pragma unroll
        for (int c = 0; c < 16; c++) {
            float4 v = row4[c];
            s  += v.x + v.y + v.z + v.w;
            s2 += v.x * v.x + v.y * v.y + v.z * v.z + v.w * v.w;
        }
        s  += __shfl_xor_sync(0xffffffffu, s, 1);
        s2 += __shfl_xor_sync(0xffffffffu, s2, 1);
        float mu   = s * (1.0f / 128.0f);
        float var  = s2 * (1.0f / 128.0f) - mu * mu;
        float rstd = rsqrtf(var + 1e-5f);
#pragma unroll
        for (int c = 0; c < 16; c++) {
            float4 v = row4[c];
            float4 g = g4[c], bb = bb4[c];
            v.x = (v.x - mu) * rstd * g.x + bb.x;
            v.y = (v.y - mu) * rstd * g.y + bb.y;
            v.z = (v.z - mu) * rstd * g.z + bb.z;
            v.w = (v.w - mu) * rstd * g.w + bb.w;
            row4[c] = v;
        }
    }
    __syncthreads();

    // --- GEMM2: out[pair][n], 8x4 per thread, K=128 blocked by 4 ---
    unsigned long long acc2[8][2];
#pragma unroll
    for (int u = 0; u < 8; u++) { acc2[u][0] = 0ull; acc2[u][1] = 0ull; }

    for (int k = 0; k < 128; k += 4) {
        float4 a4[8];
#pragma unroll
        for (int u = 0; u < 8; u++)
            a4[u] = *(const float4*)&y[(ty * 8 + u) * PAD_Y + k];
#pragma unroll
        for (int kk = 0; kk < 4; kk++) {
            ulonglong2 bv = *(const ulonglong2*)&w2s[(k + kk) * PAD_W2S + tx * 4];
#pragma unroll
            for (int u = 0; u < 8; u++) {
                float av = (&a4[u].x)[kk];
                unsigned long long ad = pack2(av, av);
                ffma2(acc2[u][0], ad, bv.x);
                ffma2(acc2[u][1], ad, bv.y);
            }
        }
    }

#pragma unroll
    for (int u = 0; u < 8; u++) {
        int pair = ty * 8 + u;
        int jj = pair & 15, ii = pair >> 4;
        float4 o;
        unpack2(acc2[u][0], o.x, o.y);
        unpack2(acc2[u][1], o.z, o.w);
        o.x += b2s[tx * 4 + 0];
        o.y += b2s[tx * 4 + 1];
        o.z += b2s[tx * 4 + 2];
        o.w += b2s[tx * 4 + 3];
        *(float4*)&out[((size_t)(i0 + ii) * Ltok + (j0 + jj)) * NBd + tx * 4] = o;
    }
}

// =============================================================================
extern "C" void kernel_launch(void* const* d_in, const int* in_sizes, int n_in,
                              void* d_out, int out_size) {
    const float* x   = (const float*)d_in[0];
    const float* Wd  = (const float*)d_in[1];
    const float* bd  = (const float*)d_in[2];
    const float* W1  = (const float*)d_in[3];
    const float* b1  = (const float*)d_in[4];
    const float* lng = (const float*)d_in[5];
    const float* lnb = (const float*)d_in[6];
    const float* W2  = (const float*)d_in[7];
    const float* b2  = (const float*)d_in[8];
    float* out = (float*)d_out;

    cudaFuncSetAttribute(k_main, cudaFuncAttributeMaxDynamicSharedMemorySize, SMEM_BYTES);

    k_down  <<<dim3(12, 8), 256>>>(x, Wd);
    k_reduce<<<384, 256>>>(bd);
    k_dqdk  <<<Ltok, 128>>>(W1, b1);
    k_main  <<<dim3(48, 96), 256, SMEM_BYTES>>>(W1, lng, lnb, W2, b2, out);
}

// round 9
// speedup vs baseline: 1.8132x; 1.5913x over previous
#include <cuda_runtime.h>
#include <cuda_bf16.h>
#include <cstdint>
#include <cstddef>

#define Ltok 768
#define Ddim 1024
#define DPd  128
#define Pp   64
#define Hd   128
#define NBd  64

__device__ float g_q [Ltok * Pp];
__device__ float g_k [Ltok * Pp];
__device__ float g_Dq[Ltok * Hd];
__device__ float g_Dk[Ltok * Hd];
__device__ float g_part[8 * Ltok * DPd];
__device__ __nv_bfloat16 g_W1hi[Hd * Pp], g_W1lo[Hd * Pp];   // [h][p] prod half
__device__ __nv_bfloat16 g_W2hi[NBd * Hd], g_W2lo[NBd * Hd]; // [n][h]

__device__ __forceinline__ unsigned long long pack2(float lo, float hi) {
    unsigned long long r;
    asm("mov.b64 %0, {%1, %2};" : "=l"(r) : "f"(lo), "f"(hi));
    return r;
}
__device__ __forceinline__ void unpack2(unsigned long long v, float& lo, float& hi) {
    asm("mov.b64 {%0, %1}, %2;" : "=f"(lo), "=f"(hi) : "l"(v));
}
__device__ __forceinline__ void ffma2(unsigned long long& acc,
                                      unsigned long long a, unsigned long long b) {
    asm("fma.rn.f32x2 %0, %1, %2, %0;" : "+l"(acc) : "l"(a), "l"(b));
}
__device__ __forceinline__ uint32_t s2u(const void* p) {
    uint32_t a;
    asm("{ .reg .u64 t; cvta.to.shared.u64 t, %1; cvt.u32.u64 %0, t; }" : "=r"(a) : "l"(p));
    return a;
}
#define LDSM4(r, addr) \
    asm volatile("ldmatrix.sync.aligned.m8n8.x4.shared.b16 {%0,%1,%2,%3}, [%4];" \
        : "=r"((r)[0]), "=r"((r)[1]), "=r"((r)[2]), "=r"((r)[3]) : "r"(addr))
#define MMA16816(c, a, b0, b1) \
    asm volatile("mma.sync.aligned.m16n8k16.row.col.f32.bf16.bf16.f32 " \
        "{%0,%1,%2,%3}, {%4,%5,%6,%7}, {%8,%9}, {%0,%1,%2,%3};" \
        : "+f"((c)[0]), "+f"((c)[1]), "+f"((c)[2]), "+f"((c)[3]) \
        : "r"((a)[0]), "r"((a)[1]), "r"((a)[2]), "r"((a)[3]), "r"(b0), "r"(b1))

__device__ __forceinline__ float gelu_exact(float x) {
    return 0.5f * x * (1.0f + erff(x * 0.70710678118654752f));
}

// ===================== kernel 1: down-proj split-K partials ==================
__global__ __launch_bounds__(256) void k_down(const float* __restrict__ x,
                                              const float* __restrict__ Wd) {
    __shared__ float xs[64][36];
    __shared__ float ws[32][132];
    const int t = threadIdx.x, tx = t & 15, ty = t >> 4;
    const int m0 = blockIdx.x * 64, kb = blockIdx.y;
    unsigned long long acc[4][4];
#pragma unroll
    for (int u = 0; u < 4; u++)
#pragma unroll
        for (int v = 0; v < 4; v++) acc[u][v] = 0ull;
    const int dbeg = kb * 128;
    for (int d0 = dbeg; d0 < dbeg + 128; d0 += 32) {
        __syncthreads();
        for (int idx = t; idx < 64 * 32; idx += 256) {
            int kk = idx & 31, mm = idx >> 5;
            xs[mm][kk] = x[(size_t)(m0 + mm) * Ddim + d0 + kk];
        }
        for (int idx = t; idx < 32 * 128; idx += 256) {
            int kk = idx & 31, p = idx >> 5;
            ws[kk][p] = Wd[(size_t)p * Ddim + d0 + kk];
        }
        __syncthreads();
#pragma unroll
        for (int k = 0; k < 32; k += 4) {
            float4 a4[4];
#pragma unroll
            for (int u = 0; u < 4; u++) a4[u] = *(const float4*)&xs[ty * 4 + u][k];
#pragma unroll
            for (int kk = 0; kk < 4; kk++) {
                const float* wrow = &ws[k + kk][tx * 8];
                ulonglong2 b0 = *(const ulonglong2*)(wrow);
                ulonglong2 b1 = *(const ulonglong2*)(wrow + 4);
#pragma unroll
                for (int u = 0; u < 4; u++) {
                    float av = (&a4[u].x)[kk];
                    unsigned long long ad = pack2(av, av);
                    ffma2(acc[u][0], ad, b0.x);
                    ffma2(acc[u][1], ad, b0.y);
                    ffma2(acc[u][2], ad, b1.x);
                    ffma2(acc[u][3], ad, b1.y);
                }
            }
        }
    }
    float* part = &g_part[(size_t)kb * Ltok * DPd];
#pragma unroll
    for (int u = 0; u < 4; u++) {
        int m = m0 + ty * 4 + u;
#pragma unroll
        for (int vp = 0; vp < 4; vp++) {
            float lo, hi;
            unpack2(acc[u][vp], lo, hi);
            part[m * DPd + tx * 8 + vp * 2]     = lo;
            part[m * DPd + tx * 8 + vp * 2 + 1] = hi;
        }
    }
}

// ===================== kernel 2: reduce + bias, split q/k =====================
__global__ __launch_bounds__(256) void k_reduce(const float* __restrict__ bd) {
    int idx = blockIdx.x * 256 + threadIdx.x;
    int p = idx & 127, m = idx >> 7;
    float s = bd[p];
#pragma unroll
    for (int r = 0; r < 8; r++) s += g_part[(size_t)r * Ltok * DPd + idx];
    if (p < Pp) g_q[m * Pp + p] = s;
    else        g_k[m * Pp + (p - Pp)] = s;
}

// ===================== kernel 3: Dq'/Dk from diff half of W1 ==================
__global__ __launch_bounds__(128) void k_dqdk(const float* __restrict__ W1,
                                              const float* __restrict__ b1) {
    const int l = blockIdx.x, h = threadIdx.x;
    __shared__ float qs[64], ks[64];
    if (h < 64) qs[h] = g_q[l * 64 + h];
    else        ks[h - 64] = g_k[l * 64 + (h - 64)];
    __syncthreads();
    float aq = b1[h], ak = 0.f;
    const float4* w4 = (const float4*)&W1[(size_t)h * DPd + Pp];
#pragma unroll
    for (int p4 = 0; p4 < 16; p4++) {
        float4 w = w4[p4];
        int b = p4 * 4;
        aq = fmaf(w.x, qs[b + 0], aq); ak = fmaf(w.x, ks[b + 0], ak);
        aq = fmaf(w.y, qs[b + 1], aq); ak = fmaf(w.y, ks[b + 1], ak);
        aq = fmaf(w.z, qs[b + 2], aq); ak = fmaf(w.z, ks[b + 2], ak);
        aq = fmaf(w.w, qs[b + 3], aq); ak = fmaf(w.w, ks[b + 3], ak);
    }
    g_Dq[l * Hd + h] = aq;
    g_Dk[l * Hd + h] = ak;
}

// ===================== kernel 3b: bf16 hi/lo weight splits ====================
__global__ __launch_bounds__(256) void k_split(const float* __restrict__ W1,
                                               const float* __restrict__ W2) {
    int idx = blockIdx.x * 256 + threadIdx.x;
    if (idx < Hd * Pp) {
        int h = idx >> 6, p = idx & 63;
        float w = W1[(size_t)h * DPd + p];
        __nv_bfloat16 hi = __float2bfloat16(w);
        g_W1hi[idx] = hi;
        g_W1lo[idx] = __float2bfloat16(w - __bfloat162float(hi));
    } else if (idx < Hd * Pp + NBd * Hd) {
        int i2 = idx - Hd * Pp;
        float w = W2[i2];
        __nv_bfloat16 hi = __float2bfloat16(w);
        g_W2hi[i2] = hi;
        g_W2lo[i2] = __float2bfloat16(w - __bfloat162float(hi));
    }
}

// ===================== kernel 4: mma.sync bf16 fused main =====================
// CTA = 128 pairs (16 j x 8 i), 256 threads, 8 warps; warp w = i-row w, 16 pairs.
// SMEM layout (bytes), XOR-swizzled padless tiles:
//   0      dq_s   16x132 f32 (8448)
//   8448   dk_s    8x132 f32 (4224)
//   12672  gln 512 | 13184 bln 512 | 13696 b2s 256
//   14336  stage1: A1hi 16K | 30720 A1lo 16K | 47104 B1hi 16K | 63488 B1lo 16K
//   stage2 overlay: 14336 A2hi 32K | 47104 A2lo 32K | 79872 B2hi 16K | 96256 B2lo 16K
//   total 112640  (2 CTAs/SM)
#define OFF_DQ    0
#define OFF_DK    8448
#define OFF_GLN   12672
#define OFF_BLN   13184
#define OFF_B2B   13696
#define OFF_A1HI  14336
#define OFF_A1LO  30720
#define OFF_B1HI  47104
#define OFF_B1LO  63488
#define OFF_A2HI  14336
#define OFF_A2LO  47104
#define OFF_B2HI  79872
#define OFF_B2LO  96256
#define SMEM_MAIN 112640

__global__ __launch_bounds__(256, 2) void k_main(const float* __restrict__ ln_g,
                                                 const float* __restrict__ ln_b,
                                                 const float* __restrict__ b2,
                                                 float* __restrict__ out) {
    extern __shared__ char smc[];
    const uint32_t sb = s2u(smc);
    const int t = threadIdx.x, wid = t >> 5, lid = t & 31;
    const int gid = lid >> 2, tig = lid & 3;
    const int j0 = blockIdx.x * 16;
    const int i0 = blockIdx.y * 8;

    float* dq_s = (float*)(smc + OFF_DQ);
    float* dk_s = (float*)(smc + OFF_DK);
    float* gln  = (float*)(smc + OFF_GLN);
    float* bln  = (float*)(smc + OFF_BLN);
    float* b2s  = (float*)(smc + OFF_B2B);

    // ---- prologue fills ----
    // A1: hin = q*k, bf16 hi/lo, 128B rows, chunk ^= row&7
    for (int idx = t; idx < 128 * 32; idx += 256) {
        int pair = idx >> 5, p2 = idx & 31, p = p2 * 2;
        int jj = pair & 15, ii = pair >> 4;
        float2 qv = *(const float2*)&g_q[(j0 + jj) * 64 + p];
        float2 kv = *(const float2*)&g_k[(i0 + ii) * 64 + p];
        float v0 = qv.x * kv.x, v1 = qv.y * kv.y;
        __nv_bfloat16 h0 = __float2bfloat16(v0), h1 = __float2bfloat16(v1);
        __nv_bfloat16 l0 = __float2bfloat16(v0 - __bfloat162float(h0));
        __nv_bfloat16 l1 = __float2bfloat16(v1 - __bfloat162float(h1));
        uint32_t byte = (uint32_t)(pair * 128 + (((p >> 3) ^ (pair & 7)) << 4) + ((p & 7) << 1));
        __nv_bfloat162 hp; hp.x = h0; hp.y = h1;
        __nv_bfloat162 lp; lp.x = l0; lp.y = l1;
        *(__nv_bfloat162*)(smc + OFF_A1HI + byte) = hp;
        *(__nv_bfloat162*)(smc + OFF_A1LO + byte) = lp;
    }
    // B1: W1 prod-half hi/lo, 128 h-rows x 64 p, 128B rows
    {
        const uint32_t* whi = (const uint32_t*)g_W1hi;
        const uint32_t* wlo = (const uint32_t*)g_W1lo;
        for (int idx = t; idx < 128 * 32; idx += 256) {
            int h = idx >> 5, p = (idx & 31) * 2;
            uint32_t byte = (uint32_t)(h * 128 + (((p >> 3) ^ (h & 7)) << 4) + ((p & 7) << 1));
            *(uint32_t*)(smc + OFF_B1HI + byte) = whi[idx];
            *(uint32_t*)(smc + OFF_B1LO + byte) = wlo[idx];
        }
    }
    // B2: W2 hi/lo, 64 n-rows x 128 h, 256B rows
    {
        const uint32_t* whi = (const uint32_t*)g_W2hi;
        const uint32_t* wlo = (const uint32_t*)g_W2lo;
        for (int idx = t; idx < 64 * 64; idx += 256) {
            int n = idx >> 6, h = (idx & 63) * 2;
            uint32_t byte = (uint32_t)(n * 256 + (((h >> 3) ^ (n & 7)) << 4) + ((h & 7) << 1));
            *(uint32_t*)(smc + OFF_B2HI + byte) = whi[idx];
            *(uint32_t*)(smc + OFF_B2LO + byte) = wlo[idx];
        }
    }
    for (int idx = t; idx < 16 * 32; idx += 256) {
        int jj = idx >> 5, c4 = idx & 31;
        *(float4*)&dq_s[jj * 132 + c4 * 4] = *(const float4*)&g_Dq[(j0 + jj) * 128 + c4 * 4];
    }
    for (int idx = t; idx < 8 * 32; idx += 256) {
        int ii = idx >> 5, c4 = idx & 31;
        *(float4*)&dk_s[ii * 132 + c4 * 4] = *(const float4*)&g_Dk[(i0 + ii) * 128 + c4 * 4];
    }
    if (t < 64)  b2s[t] = b2[t];
    if (t < 128) gln[t] = ln_g[t];
    else         bln[t - 128] = ln_b[t - 128];
    __syncthreads();

    // ---- GEMM1: acc1[pair 16w..+16][h 0..128], 3-term bf16 ----
    float acc1[16][4];
#pragma unroll
    for (int n = 0; n < 16; n++)
#pragma unroll
        for (int c = 0; c < 4; c++) acc1[n][c] = 0.f;

    const int pair0 = wid * 16;
#pragma unroll
    for (int ks = 0; ks < 4; ks++) {
        uint32_t ah[4], al[4];
        {
            int row = pair0 + (lid & 15);
            int chunk = ks * 2 + (lid >> 4);
            uint32_t ad = sb + OFF_A1HI + row * 128 + ((chunk ^ (row & 7)) << 4);
            LDSM4(ah, ad);
            LDSM4(al, ad + (OFF_A1LO - OFF_A1HI));
        }
        int brow = (lid & 7) + ((lid >> 4) << 3);
        int bchunk = ks * 2 + ((lid >> 3) & 1);
#pragma unroll
        for (int np = 0; np < 8; np++) {
            int row = np * 16 + brow;
            uint32_t bd = sb + OFF_B1HI + row * 128 + ((bchunk ^ (row & 7)) << 4);
            uint32_t bh[4], bl[4];
            LDSM4(bh, bd);
            LDSM4(bl, bd + (OFF_B1LO - OFF_B1HI));
            MMA16816(acc1[2 * np],     ah, bh[0], bh[1]);
            MMA16816(acc1[2 * np + 1], ah, bh[2], bh[3]);
            MMA16816(acc1[2 * np],     ah, bl[0], bl[1]);
            MMA16816(acc1[2 * np + 1], ah, bl[2], bl[3]);
            MMA16816(acc1[2 * np],     al, bh[0], bh[1]);
            MMA16816(acc1[2 * np + 1], al, bh[2], bh[3]);
        }
    }

    // ---- epilogue pass A: +Dq-Dk, exact GELU, row stats ----
    float mu[2], rs[2];
#pragma unroll
    for (int r = 0; r < 2; r++) {
        int prow = pair0 + gid + 8 * r;
        int jj = prow & 15;
        const float* dqr = &dq_s[jj * 132];
        const float* dkr = &dk_s[wid * 132];
        float s = 0.f, s2 = 0.f;
#pragma unroll
        for (int nt = 0; nt < 16; nt++) {
            int col = nt * 8 + tig * 2;
            float2 dq = *(const float2*)&dqr[col];
            float2 dk = *(const float2*)&dkr[col];
            float g0 = gelu_exact(acc1[nt][2 * r]     + dq.x - dk.x);
            float g1 = gelu_exact(acc1[nt][2 * r + 1] + dq.y - dk.y);
            s += g0 + g1; s2 += g0 * g0 + g1 * g1;
            acc1[nt][2 * r] = g0; acc1[nt][2 * r + 1] = g1;
        }
        s  += __shfl_xor_sync(0xffffffffu, s, 1);
        s  += __shfl_xor_sync(0xffffffffu, s, 2);
        s2 += __shfl_xor_sync(0xffffffffu, s2, 1);
        s2 += __shfl_xor_sync(0xffffffffu, s2, 2);
        mu[r] = s * (1.0f / 128.0f);
        float var = s2 * (1.0f / 128.0f) - mu[r] * mu[r];
        rs[r] = rsqrtf(var + 1e-5f);
    }
    __syncthreads();   // all warps done reading stage-1 tiles

    // ---- epilogue pass B: LN, bf16 split -> A2 (256B rows, swizzled) ----
#pragma unroll
    for (int r = 0; r < 2; r++) {
        int prow = pair0 + gid + 8 * r;
        uint32_t rbase = (uint32_t)(prow * 256);
        uint32_t rx = (uint32_t)(prow & 7);
#pragma unroll
        for (int nt = 0; nt < 16; nt++) {
            int col = nt * 8 + tig * 2;
            float2 g2 = *(const float2*)&gln[col];
            float2 b2l = *(const float2*)&bln[col];
            float z0 = (acc1[nt][2 * r]     - mu[r]) * rs[r] * g2.x + b2l.x;
            float z1 = (acc1[nt][2 * r + 1] - mu[r]) * rs[r] * g2.y + b2l.y;
            __nv_bfloat16 h0 = __float2bfloat16(z0), h1 = __float2bfloat16(z1);
            __nv_bfloat16 l0 = __float2bfloat16(z0 - __bfloat162float(h0));
            __nv_bfloat16 l1 = __float2bfloat16(z1 - __bfloat162float(h1));
            uint32_t byte = rbase + ((((uint32_t)(col >> 3)) ^ rx) << 4) + ((col & 7) << 1);
            __nv_bfloat162 hp; hp.x = h0; hp.y = h1;
            __nv_bfloat162 lp; lp.x = l0; lp.y = l1;
            *(__nv_bfloat162*)(smc + OFF_A2HI + byte) = hp;
            *(__nv_bfloat162*)(smc + OFF_A2LO + byte) = lp;
        }
    }
    __syncthreads();

    // ---- GEMM2: acc2[pair][n 0..64], K=128, 3-term bf16 ----
    float acc2[8][4];
#pragma unroll
    for (int n = 0; n < 8; n++)
#pragma unroll
        for (int c = 0; c < 4; c++) acc2[n][c] = 0.f;

#pragma unroll
    for (int ks = 0; ks < 8; ks++) {
        uint32_t ah[4], al[4];
        {
            int row = pair0 + (lid & 15);
            int chunk = ks * 2 + (lid >> 4);
            uint32_t ad = sb + OFF_A2HI + row * 256 + ((chunk ^ (row & 7)) << 4);
            LDSM4(ah, ad);
            LDSM4(al, ad + (OFF_A2LO - OFF_A2HI));
        }
        int brow = (lid & 7) + ((lid >> 4) << 3);
        int bchunk = ks * 2 + ((lid >> 3) & 1);
#pragma unroll
        for (int np = 0; np < 4; np++) {
            int row = np * 16 + brow;
            uint32_t bd = sb + OFF_B2HI + row * 256 + ((bchunk ^ (row & 7)) << 4);
            uint32_t bh[4], bl[4];
            LDSM4(bh, bd);
            LDSM4(bl, bd + (OFF_B2LO - OFF_B2HI));
            MMA16816(acc2[2 * np],     ah, bh[0], bh[1]);
            MMA16816(acc2[2 * np + 1], ah, bh[2], bh[3]);
            MMA16816(acc2[2 * np],     ah, bl[0], bl[1]);
            MMA16816(acc2[2 * np + 1], ah, bl[2], bl[3]);
            MMA16816(acc2[2 * np],     al, bh[0], bh[1]);
            MMA16816(acc2[2 * np + 1], al, bh[2], bh[3]);
        }
    }

    // ---- output: + b2 ----
#pragma unroll
    for (int r = 0; r < 2; r++) {
        int prow = pair0 + gid + 8 * r;
        int jj = prow & 15;
        float* op = &out[((size_t)(i0 + wid) * Ltok + (j0 + jj)) * NBd];
#pragma unroll
        for (int nt = 0; nt < 8; nt++) {
            int col = nt * 8 + tig * 2;
            float2 bb = *(const float2*)&b2s[col];
            float2 o;
            o.x = acc2[nt][2 * r]     + bb.x;
            o.y = acc2[nt][2 * r + 1] + bb.y;
            *(float2*)&op[col] = o;
        }
    }
}

// =============================================================================
extern "C" void kernel_launch(void* const* d_in, const int* in_sizes, int n_in,
                              void* d_out, int out_size) {
    const float* x   = (const float*)d_in[0];
    const float* Wd  = (const float*)d_in[1];
    const float* bd  = (const float*)d_in[2];
    const float* W1  = (const float*)d_in[3];
    const float* b1  = (const float*)d_in[4];
    const float* lng = (const float*)d_in[5];
    const float* lnb = (const float*)d_in[6];
    const float* W2  = (const float*)d_in[7];
    const float* b2  = (const float*)d_in[8];
    float* out = (float*)d_out;

    cudaFuncSetAttribute(k_main, cudaFuncAttributeMaxDynamicSharedMemorySize, SMEM_MAIN);

    k_down  <<<dim3(12, 8), 256>>>(x, Wd);
    k_reduce<<<384, 256>>>(bd);
    k_dqdk  <<<Ltok, 128>>>(W1, b1);
    k_split <<<64, 256>>>(W1, W2);
    k_main  <<<dim3(48, 96), 256, SMEM_MAIN>>>(lng, lnb, b2, out);
}

// round 10
// speedup vs baseline: 1.8592x; 1.0254x over previous
#include <cuda_runtime.h>
#include <cuda_bf16.h>
#include <cstdint>
#include <cstddef>

#define Ltok 768
#define Ddim 1024
#define DPd  128
#define Pp   64
#define Hd   128
#define NBd  64

__device__ float g_q [Ltok * Pp];
__device__ float g_k [Ltok * Pp];
__device__ float g_Dq[Ltok * Hd];
__device__ float g_Dk[Ltok * Hd];
__device__ float g_part[8 * Ltok * DPd];
__device__ __nv_bfloat16 g_W1hi[Hd * Pp],  g_W1lo[Hd * Pp];   // [h][p] prod half
__device__ __nv_bfloat16 g_W2ghi[NBd * Hd], g_W2glo[NBd * Hd]; // (g*W2)[n][h]
__device__ float g_Gvec[NBd];   // sum_h ln_g[h] * W2[n][h]
__device__ float g_Cvec[NBd];   // sum_h ln_b[h] * W2[n][h] + b2[n]

__device__ __forceinline__ unsigned long long pack2(float lo, float hi) {
    unsigned long long r;
    asm("mov.b64 %0, {%1, %2};" : "=l"(r) : "f"(lo), "f"(hi));
    return r;
}
__device__ __forceinline__ void unpack2(unsigned long long v, float& lo, float& hi) {
    asm("mov.b64 {%0, %1}, %2;" : "=f"(lo), "=f"(hi) : "l"(v));
}
__device__ __forceinline__ void ffma2(unsigned long long& acc,
                                      unsigned long long a, unsigned long long b) {
    asm("fma.rn.f32x2 %0, %1, %2, %0;" : "+l"(acc) : "l"(a), "l"(b));
}
__device__ __forceinline__ uint32_t s2u(const void* p) {
    uint32_t a;
    asm("{ .reg .u64 t; cvta.to.shared.u64 t, %1; cvt.u32.u64 %0, t; }" : "=r"(a) : "l"(p));
    return a;
}
#define LDSM4(r, addr) \
    asm volatile("ldmatrix.sync.aligned.m8n8.x4.shared.b16 {%0,%1,%2,%3}, [%4];" \
        : "=r"((r)[0]), "=r"((r)[1]), "=r"((r)[2]), "=r"((r)[3]) : "r"(addr))
#define MMA16816(c, a, b0, b1) \
    asm volatile("mma.sync.aligned.m16n8k16.row.col.f32.bf16.bf16.f32 " \
        "{%0,%1,%2,%3}, {%4,%5,%6,%7}, {%8,%9}, {%0,%1,%2,%3};" \
        : "+f"((c)[0]), "+f"((c)[1]), "+f"((c)[2]), "+f"((c)[3]) \
        : "r"((a)[0]), "r"((a)[1]), "r"((a)[2]), "r"((a)[3]), "r"(b0), "r"(b1))

__device__ __forceinline__ float gelu_exact(float x) {
    return 0.5f * x * (1.0f + erff(x * 0.70710678118654752f));
}

// ===================== kernel 1: down-proj split-K partials ==================
__global__ __launch_bounds__(256) void k_down(const float* __restrict__ x,
                                              const float* __restrict__ Wd) {
    __shared__ float xs[64][36];
    __shared__ float ws[32][132];
    const int t = threadIdx.x, tx = t & 15, ty = t >> 4;
    const int m0 = blockIdx.x * 64, kb = blockIdx.y;
    unsigned long long acc[4][4];
#pragma unroll
    for (int u = 0; u < 4; u++)
#pragma unroll
        for (int v = 0; v < 4; v++) acc[u][v] = 0ull;
    const int dbeg = kb * 128;
    for (int d0 = dbeg; d0 < dbeg + 128; d0 += 32) {
        __syncthreads();
        for (int idx = t; idx < 64 * 32; idx += 256) {
            int kk = idx & 31, mm = idx >> 5;
            xs[mm][kk] = x[(size_t)(m0 + mm) * Ddim + d0 + kk];
        }
        for (int idx = t; idx < 32 * 128; idx += 256) {
            int kk = idx & 31, p = idx >> 5;
            ws[kk][p] = Wd[(size_t)p * Ddim + d0 + kk];
        }
        __syncthreads();
#pragma unroll
        for (int k = 0; k < 32; k += 4) {
            float4 a4[4];
#pragma unroll
            for (int u = 0; u < 4; u++) a4[u] = *(const float4*)&xs[ty * 4 + u][k];
#pragma unroll
            for (int kk = 0; kk < 4; kk++) {
                const float* wrow = &ws[k + kk][tx * 8];
                ulonglong2 b0 = *(const ulonglong2*)(wrow);
                ulonglong2 b1 = *(const ulonglong2*)(wrow + 4);
#pragma unroll
                for (int u = 0; u < 4; u++) {
                    float av = (&a4[u].x)[kk];
                    unsigned long long ad = pack2(av, av);
                    ffma2(acc[u][0], ad, b0.x);
                    ffma2(acc[u][1], ad, b0.y);
                    ffma2(acc[u][2], ad, b1.x);
                    ffma2(acc[u][3], ad, b1.y);
                }
            }
        }
    }
    float* part = &g_part[(size_t)kb * Ltok * DPd];
#pragma unroll
    for (int u = 0; u < 4; u++) {
        int m = m0 + ty * 4 + u;
#pragma unroll
        for (int vp = 0; vp < 4; vp++) {
            float lo, hi;
            unpack2(acc[u][vp], lo, hi);
            part[m * DPd + tx * 8 + vp * 2]     = lo;
            part[m * DPd + tx * 8 + vp * 2 + 1] = hi;
        }
    }
}

// ===================== kernel 2 (fused mid): reduce+dqdk | weight splits ======
// blocks 0..767   : row l = blk — split-K reduce + bias -> q,k ; then Dq/Dk
// blocks 768..831 : W1 prod-half bf16 hi/lo split (8192 elems)
// blocks 832..895 : (ln_g * W2) bf16 hi/lo split (8192 elems)
// block  896      : G[n], C[n] vectors
__global__ __launch_bounds__(128) void k_mid(const float* __restrict__ bd,
                                             const float* __restrict__ W1,
                                             const float* __restrict__ b1,
                                             const float* __restrict__ W2,
                                             const float* __restrict__ lng,
                                             const float* __restrict__ lnb,
                                             const float* __restrict__ b2) {
    const int blk = blockIdx.x, t = threadIdx.x;
    if (blk < Ltok) {
        const int l = blk;
        __shared__ float qs[64], ks[64];
        float s = bd[t];
        const int idx = l * DPd + t;
#pragma unroll
        for (int r = 0; r < 8; r++) s += g_part[(size_t)r * Ltok * DPd + idx];
        if (t < 64) { qs[t] = s;      g_q[l * Pp + t] = s; }
        else        { ks[t - 64] = s; g_k[l * Pp + (t - 64)] = s; }
        __syncthreads();
        float aq = b1[t], ak = 0.f;
        const float4* w4 = (const float4*)&W1[(size_t)t * DPd + Pp];
#pragma unroll
        for (int p4 = 0; p4 < 16; p4++) {
            float4 w = w4[p4];
            int b = p4 * 4;
            aq = fmaf(w.x, qs[b + 0], aq); ak = fmaf(w.x, ks[b + 0], ak);
            aq = fmaf(w.y, qs[b + 1], aq); ak = fmaf(w.y, ks[b + 1], ak);
            aq = fmaf(w.z, qs[b + 2], aq); ak = fmaf(w.z, ks[b + 2], ak);
            aq = fmaf(w.w, qs[b + 3], aq); ak = fmaf(w.w, ks[b + 3], ak);
        }
        g_Dq[l * Hd + t] = aq;
        g_Dk[l * Hd + t] = ak;
    } else if (blk < Ltok + 64) {
        int i = (blk - Ltok) * 128 + t;          // < 8192
        int h = i >> 6, p = i & 63;
        float w = W1[(size_t)h * DPd + p];
        __nv_bfloat16 hi = __float2bfloat16(w);
        g_W1hi[i] = hi;
        g_W1lo[i] = __float2bfloat16(w - __bfloat162float(hi));
    } else if (blk < Ltok + 128) {
        int i = (blk - Ltok - 64) * 128 + t;     // i = n*128 + h
        float w = W2[i] * lng[i & 127];
        __nv_bfloat16 hi = __float2bfloat16(w);
        g_W2ghi[i] = hi;
        g_W2glo[i] = __float2bfloat16(w - __bfloat162float(hi));
    } else {
        if (t < NBd) {
            float G = 0.f, C = 0.f;
            const float* wr = &W2[(size_t)t * Hd];
#pragma unroll 4
            for (int h = 0; h < Hd; h++) {
                float w = wr[h];
                G = fmaf(w, lng[h], G);
                C = fmaf(w, lnb[h], C);
            }
            g_Gvec[t] = G;
            g_Cvec[t] = C + b2[t];
        }
    }
}

// ===================== kernel 3: mma.sync bf16 fused main =====================
// CTA = 128 pairs (16 j x 8 i), 256 threads, 8 warps; warp w = i-row w, 16 pairs.
// out = rstd*(gelu(h) @ (g*W2)^T - mu*G) + C   (LN folded into GEMM2 epilogue)
// SMEM (bytes): 0 dq_s 16x132f (8448) | 8448 dk_s 8x132f (4224)
//   12672 Gs 256 | 12928 Cs 256
//   14336 stage1: A1hi 16K | 30720 A1lo 16K | 47104 B1hi 16K | 63488 B1lo 16K
//   stage2 overlay: 14336 A2hi 32K | 47104 A2lo 32K | 79872 B2hi 16K | 96256 B2lo 16K
//   total 112640 (2 CTAs/SM)
#define OFF_DQ    0
#define OFF_DK    8448
#define OFF_GS    12672
#define OFF_CS    12928
#define OFF_A1HI  14336
#define OFF_A1LO  30720
#define OFF_B1HI  47104
#define OFF_B1LO  63488
#define OFF_A2HI  14336
#define OFF_A2LO  47104
#define OFF_B2HI  79872
#define OFF_B2LO  96256
#define SMEM_MAIN 112640

__global__ __launch_bounds__(256, 2) void k_main(float* __restrict__ out) {
    extern __shared__ char smc[];
    const uint32_t sb = s2u(smc);
    const int t = threadIdx.x, wid = t >> 5, lid = t & 31;
    const int gid = lid >> 2, tig = lid & 3;
    const int j0 = blockIdx.x * 16;
    const int i0 = blockIdx.y * 8;

    float* dq_s = (float*)(smc + OFF_DQ);
    float* dk_s = (float*)(smc + OFF_DK);
    float* Gs   = (float*)(smc + OFF_GS);
    float* Cs   = (float*)(smc + OFF_CS);

    // ---- prologue fills ----
    for (int idx = t; idx < 128 * 32; idx += 256) {
        int pair = idx >> 5, p = (idx & 31) * 2;
        int jj = pair & 15, ii = pair >> 4;
        float2 qv = *(const float2*)&g_q[(j0 + jj) * 64 + p];
        float2 kv = *(const float2*)&g_k[(i0 + ii) * 64 + p];
        float v0 = qv.x * kv.x, v1 = qv.y * kv.y;
        __nv_bfloat16 h0 = __float2bfloat16(v0), h1 = __float2bfloat16(v1);
        __nv_bfloat16 l0 = __float2bfloat16(v0 - __bfloat162float(h0));
        __nv_bfloat16 l1 = __float2bfloat16(v1 - __bfloat162float(h1));
        uint32_t byte = (uint32_t)(pair * 128 + (((p >> 3) ^ (pair & 7)) << 4) + ((p & 7) << 1));
        __nv_bfloat162 hp; hp.x = h0; hp.y = h1;
        __nv_bfloat162 lp; lp.x = l0; lp.y = l1;
        *(__nv_bfloat162*)(smc + OFF_A1HI + byte) = hp;
        *(__nv_bfloat162*)(smc + OFF_A1LO + byte) = lp;
    }
    {
        const uint32_t* whi = (const uint32_t*)g_W1hi;
        const uint32_t* wlo = (const uint32_t*)g_W1lo;
        for (int idx = t; idx < 128 * 32; idx += 256) {
            int h = idx >> 5, p = (idx & 31) * 2;
            uint32_t byte = (uint32_t)(h * 128 + (((p >> 3) ^ (h & 7)) << 4) + ((p & 7) << 1));
            *(uint32_t*)(smc + OFF_B1HI + byte) = whi[idx];
            *(uint32_t*)(smc + OFF_B1LO + byte) = wlo[idx];
        }
    }
    {
        const uint32_t* whi = (const uint32_t*)g_W2ghi;
        const uint32_t* wlo = (const uint32_t*)g_W2glo;
        for (int idx = t; idx < 64 * 64; idx += 256) {
            int n = idx >> 6, h = (idx & 63) * 2;
            uint32_t byte = (uint32_t)(n * 256 + (((h >> 3) ^ (n & 7)) << 4) + ((h & 7) << 1));
            *(uint32_t*)(smc + OFF_B2HI + byte) = whi[idx];
            *(uint32_t*)(smc + OFF_B2LO + byte) = wlo[idx];
        }
    }
    for (int idx = t; idx < 16 * 32; idx += 256) {
        int jj = idx >> 5, c4 = idx & 31;
        *(float4*)&dq_s[jj * 132 + c4 * 4] = *(const float4*)&g_Dq[(j0 + jj) * 128 + c4 * 4];
    }
    for (int idx = t; idx < 8 * 32; idx += 256) {
        int ii = idx >> 5, c4 = idx & 31;
        *(float4*)&dk_s[ii * 132 + c4 * 4] = *(const float4*)&g_Dk[(i0 + ii) * 128 + c4 * 4];
    }
    if (t < 64)       Gs[t] = g_Gvec[t];
    else if (t < 128) Cs[t - 64] = g_Cvec[t - 64];
    __syncthreads();

    // ---- GEMM1: acc1[16 n-tiles of 8h][4], 3-term bf16 ----
    float acc1[16][4];
#pragma unroll
    for (int n = 0; n < 16; n++)
#pragma unroll
        for (int c = 0; c < 4; c++) acc1[n][c] = 0.f;

    const int pair0 = wid * 16;
#pragma unroll
    for (int ks = 0; ks < 4; ks++) {
        uint32_t ah[4], al[4];
        {
            int row = pair0 + (lid & 15);
            int chunk = ks * 2 + (lid >> 4);
            uint32_t ad = sb + OFF_A1HI + row * 128 + ((chunk ^ (row & 7)) << 4);
            LDSM4(ah, ad);
            LDSM4(al, ad + (OFF_A1LO - OFF_A1HI));
        }
        int brow = (lid & 7) + ((lid >> 4) << 3);
        int bchunk = ks * 2 + ((lid >> 3) & 1);
#pragma unroll
        for (int np = 0; np < 8; np++) {
            int row = np * 16 + brow;
            uint32_t bd = sb + OFF_B1HI + row * 128 + ((bchunk ^ (row & 7)) << 4);
            uint32_t bh[4], bl[4];
            LDSM4(bh, bd);
            LDSM4(bl, bd + (OFF_B1LO - OFF_B1HI));
            MMA16816(acc1[2 * np],     ah, bh[0], bh[1]);
            MMA16816(acc1[2 * np + 1], ah, bh[2], bh[3]);
            MMA16816(acc1[2 * np],     ah, bl[0], bl[1]);
            MMA16816(acc1[2 * np + 1], ah, bl[2], bl[3]);
            MMA16816(acc1[2 * np],     al, bh[0], bh[1]);
            MMA16816(acc1[2 * np + 1], al, bh[2], bh[3]);
        }
    }

    // ---- epilogue pass A: +Dq-Dk, exact GELU, row stats ----
    float mu[2], rs[2];
#pragma unroll
    for (int r = 0; r < 2; r++) {
        int prow = pair0 + gid + 8 * r;
        int jj = prow & 15;
        const float* dqr = &dq_s[jj * 132];
        const float* dkr = &dk_s[wid * 132];
        float s = 0.f, s2 = 0.f;
#pragma unroll
        for (int nt = 0; nt < 16; nt++) {
            int col = nt * 8 + tig * 2;
            float2 dq = *(const float2*)&dqr[col];
            float2 dk = *(const float2*)&dkr[col];
            float g0 = gelu_exact(acc1[nt][2 * r]     + dq.x - dk.x);
            float g1 = gelu_exact(acc1[nt][2 * r + 1] + dq.y - dk.y);
            s += g0 + g1; s2 += g0 * g0 + g1 * g1;
            acc1[nt][2 * r] = g0; acc1[nt][2 * r + 1] = g1;
        }
        s  += __shfl_xor_sync(0xffffffffu, s, 1);
        s  += __shfl_xor_sync(0xffffffffu, s, 2);
        s2 += __shfl_xor_sync(0xffffffffu, s2, 1);
        s2 += __shfl_xor_sync(0xffffffffu, s2, 2);
        mu[r] = s * (1.0f / 128.0f);
        float var = s2 * (1.0f / 128.0f) - mu[r] * mu[r];
        rs[r] = rsqrtf(var + 1e-5f);
    }
    __syncthreads();   // all warps done reading stage-1 tiles

    // ---- epilogue pass B: bf16 split of gelu(h) -> A2 (LN folded out) ----
#pragma unroll
    for (int r = 0; r < 2; r++) {
        int prow = pair0 + gid + 8 * r;
        uint32_t rbase = (uint32_t)(prow * 256);
        uint32_t rx = (uint32_t)(prow & 7);
#pragma unroll
        for (int nt = 0; nt < 16; nt++) {
            int col = nt * 8 + tig * 2;
            float z0 = acc1[nt][2 * r], z1 = acc1[nt][2 * r + 1];
            __nv_bfloat16 h0 = __float2bfloat16(z0), h1 = __float2bfloat16(z1);
            __nv_bfloat16 l0 = __float2bfloat16(z0 - __bfloat162float(h0));
            __nv_bfloat16 l1 = __float2bfloat16(z1 - __bfloat162float(h1));
            uint32_t byte = rbase + ((((uint32_t)(col >> 3)) ^ rx) << 4) + ((col & 7) << 1);
            __nv_bfloat162 hp; hp.x = h0; hp.y = h1;
            __nv_bfloat162 lp; lp.x = l0; lp.y = l1;
            *(__nv_bfloat162*)(smc + OFF_A2HI + byte) = hp;
            *(__nv_bfloat162*)(smc + OFF_A2LO + byte) = lp;
        }
    }
    __syncthreads();

    // ---- GEMM2: acc2[pair][n 0..64], K=128, 3-term bf16 ----
    float acc2[8][4];
#pragma unroll
    for (int n = 0; n < 8; n++)
#pragma unroll
        for (int c = 0; c < 4; c++) acc2[n][c] = 0.f;

#pragma unroll
    for (int ks = 0; ks < 8; ks++) {
        uint32_t ah[4], al[4];
        {
            int row = pair0 + (lid & 15);
            int chunk = ks * 2 + (lid >> 4);
            uint32_t ad = sb + OFF_A2HI + row * 256 + ((chunk ^ (row & 7)) << 4);
            LDSM4(ah, ad);
            LDSM4(al, ad + (OFF_A2LO - OFF_A2HI));
        }
        int brow = (lid & 7) + ((lid >> 4) << 3);
        int bchunk = ks * 2 + ((lid >> 3) & 1);
#pragma unroll
        for (int np = 0; np < 4; np++) {
            int row = np * 16 + brow;
            uint32_t bd = sb + OFF_B2HI + row * 256 + ((bchunk ^ (row & 7)) << 4);
            uint32_t bh[4], bl[4];
            LDSM4(bh, bd);
            LDSM4(bl, bd + (OFF_B2LO - OFF_B2HI));
            MMA16816(acc2[2 * np],     ah, bh[0], bh[1]);
            MMA16816(acc2[2 * np + 1], ah, bh[2], bh[3]);
            MMA16816(acc2[2 * np],     ah, bl[0], bl[1]);
            MMA16816(acc2[2 * np + 1], ah, bl[2], bl[3]);
            MMA16816(acc2[2 * np],     al, bh[0], bh[1]);
            MMA16816(acc2[2 * np + 1], al, bh[2], bh[3]);
        }
    }

    // ---- output: rstd*(acc2 - mu*G) + C ----
#pragma unroll
    for (int r = 0; r < 2; r++) {
        int prow = pair0 + gid + 8 * r;
        int jj = prow & 15;
        float* op = &out[((size_t)(i0 + wid) * Ltok + (j0 + jj)) * NBd];
#pragma unroll
        for (int nt = 0; nt < 8; nt++) {
            int col = nt * 8 + tig * 2;
            float2 G2 = *(const float2*)&Gs[col];
            float2 C2 = *(const float2*)&Cs[col];
            float2 o;
            o.x = rs[r] * (acc2[nt][2 * r]     - mu[r] * G2.x) + C2.x;
            o.y = rs[r] * (acc2[nt][2 * r + 1] - mu[r] * G2.y) + C2.y;
            *(float2*)&op[col] = o;
        }
    }
}

// =============================================================================
extern "C" void kernel_launch(void* const* d_in, const int* in_sizes, int n_in,
                              void* d_out, int out_size) {
    const float* x   = (const float*)d_in[0];
    const float* Wd  = (const float*)d_in[1];
    const float* bd  = (const float*)d_in[2];
    const float* W1  = (const float*)d_in[3];
    const float* b1  = (const float*)d_in[4];
    const float* lng = (const float*)d_in[5];
    const float* lnb = (const float*)d_in[6];
    const float* W2  = (const float*)d_in[7];
    const float* b2  = (const float*)d_in[8];
    float* out = (float*)d_out;

    cudaFuncSetAttribute(k_main, cudaFuncAttributeMaxDynamicSharedMemorySize, SMEM_MAIN);

    k_down<<<dim3(12, 8), 256>>>(x, Wd);
    k_mid <<<Ltok + 129, 128>>>(bd, W1, b1, W2, lng, lnb, b2);
    k_main<<<dim3(48, 96), 256, SMEM_MAIN>>>(out);
}

// round 11
// speedup vs baseline: 2.1236x; 1.1422x over previous
#include <cuda_runtime.h>
#include <cuda_bf16.h>
#include <cstdint>
#include <cstddef>

#define Ltok 768
#define Ddim 1024
#define DPd  128
#define Pp   64
#define Hd   128
#define NBd  64
#define NKB  16   // split-K slices in k_down

__device__ float g_q [Ltok * Pp];
__device__ float g_k [Ltok * Pp];
__device__ float g_Dq[Ltok * Hd];
__device__ float g_Dk[Ltok * Hd];
__device__ float g_part[NKB * Ltok * DPd];
__device__ float g_W1t [Hd * Pp];    // tf32-rounded W1 prod half, [h][p]
__device__ float g_W2gt[NBd * Hd];   // tf32-rounded (ln_g * W2), [n][h]
__device__ float g_Gvec[NBd];
__device__ float g_Cvec[NBd];

__device__ __forceinline__ unsigned long long pack2(float lo, float hi) {
    unsigned long long r;
    asm("mov.b64 %0, {%1, %2};" : "=l"(r) : "f"(lo), "f"(hi));
    return r;
}
__device__ __forceinline__ void unpack2(unsigned long long v, float& lo, float& hi) {
    asm("mov.b64 {%0, %1}, %2;" : "=f"(lo), "=f"(hi) : "l"(v));
}
__device__ __forceinline__ void ffma2(unsigned long long& acc,
                                      unsigned long long a, unsigned long long b) {
    asm("fma.rn.f32x2 %0, %1, %2, %0;" : "+l"(acc) : "l"(a), "l"(b));
}
__device__ __forceinline__ uint32_t s2u(const void* p) {
    uint32_t a;
    asm("{ .reg .u64 t; cvta.to.shared.u64 t, %1; cvt.u32.u64 %0, t; }" : "=r"(a) : "l"(p));
    return a;
}
__device__ __forceinline__ uint32_t f2tf(float x) {
    uint32_t r;
    asm("cvt.rna.tf32.f32 %0, %1;" : "=r"(r) : "f"(x));
    return r;
}
#define LDSM4(r, addr) \
    asm volatile("ldmatrix.sync.aligned.m8n8.x4.shared.b16 {%0,%1,%2,%3}, [%4];" \
        : "=r"((r)[0]), "=r"((r)[1]), "=r"((r)[2]), "=r"((r)[3]) : "r"(addr))
#define MMAT(c, a, b0, b1) \
    asm volatile("mma.sync.aligned.m16n8k8.row.col.f32.tf32.tf32.f32 " \
        "{%0,%1,%2,%3}, {%4,%5,%6,%7}, {%8,%9}, {%0,%1,%2,%3};" \
        : "+f"((c)[0]), "+f"((c)[1]), "+f"((c)[2]), "+f"((c)[3]) \
        : "r"((a)[0]), "r"((a)[1]), "r"((a)[2]), "r"((a)[3]), "r"(b0), "r"(b1))

__device__ __forceinline__ float gelu_exact(float x) {
    return 0.5f * x * (1.0f + erff(x * 0.70710678118654752f));
}

// ===================== kernel 1: down-proj split-K partials ==================
// grid (12, 16): 64 rows x 128 cols per block, K-slice of 64.
__global__ __launch_bounds__(256) void k_down(const float* __restrict__ x,
                                              const float* __restrict__ Wd) {
    __shared__ float xs[64][36];
    __shared__ float ws[32][132];
    const int t = threadIdx.x, tx = t & 15, ty = t >> 4;
    const int m0 = blockIdx.x * 64, kb = blockIdx.y;
    unsigned long long acc[4][4];
#pragma unroll
    for (int u = 0; u < 4; u++)
#pragma unroll
        for (int v = 0; v < 4; v++) acc[u][v] = 0ull;
    const int dbeg = kb * 64;
    for (int d0 = dbeg; d0 < dbeg + 64; d0 += 32) {
        __syncthreads();
        for (int idx = t; idx < 64 * 32; idx += 256) {
            int kk = idx & 31, mm = idx >> 5;
            xs[mm][kk] = x[(size_t)(m0 + mm) * Ddim + d0 + kk];
        }
        for (int idx = t; idx < 32 * 128; idx += 256) {
            int kk = idx & 31, p = idx >> 5;
            ws[kk][p] = Wd[(size_t)p * Ddim + d0 + kk];
        }
        __syncthreads();
#pragma unroll
        for (int k = 0; k < 32; k += 4) {
            float4 a4[4];
#pragma unroll
            for (int u = 0; u < 4; u++) a4[u] = *(const float4*)&xs[ty * 4 + u][k];
#pragma unroll
            for (int kk = 0; kk < 4; kk++) {
                const float* wrow = &ws[k + kk][tx * 8];
                ulonglong2 b0 = *(const ulonglong2*)(wrow);
                ulonglong2 b1 = *(const ulonglong2*)(wrow + 4);
#pragma unroll
                for (int u = 0; u < 4; u++) {
                    float av = (&a4[u].x)[kk];
                    unsigned long long ad = pack2(av, av);
                    ffma2(acc[u][0], ad, b0.x);
                    ffma2(acc[u][1], ad, b0.y);
                    ffma2(acc[u][2], ad, b1.x);
                    ffma2(acc[u][3], ad, b1.y);
                }
            }
        }
    }
    float* part = &g_part[(size_t)kb * Ltok * DPd];
#pragma unroll
    for (int u = 0; u < 4; u++) {
        int m = m0 + ty * 4 + u;
#pragma unroll
        for (int vp = 0; vp < 4; vp++) {
            float lo, hi;
            unpack2(acc[u][vp], lo, hi);
            part[m * DPd + tx * 8 + vp * 2]     = lo;
            part[m * DPd + tx * 8 + vp * 2 + 1] = hi;
        }
    }
}

// ===================== kernel 2 (fused mid) ===================================
// blocks 0..767   : row l — split-K reduce + bias -> q,k ; then Dq/Dk
// blocks 768..831 : W1 prod-half tf32 rounding (8192 elems)
// blocks 832..895 : (ln_g * W2) tf32 rounding (8192 elems)
// block  896      : G[n], C[n]
__global__ __launch_bounds__(128) void k_mid(const float* __restrict__ bd,
                                             const float* __restrict__ W1,
                                             const float* __restrict__ b1,
                                             const float* __restrict__ W2,
                                             const float* __restrict__ lng,
                                             const float* __restrict__ lnb,
                                             const float* __restrict__ b2) {
    const int blk = blockIdx.x, t = threadIdx.x;
    if (blk < Ltok) {
        const int l = blk;
        __shared__ float qs[64], ks[64];
        float s = bd[t];
        const int idx = l * DPd + t;
#pragma unroll
        for (int r = 0; r < NKB; r++) s += g_part[(size_t)r * Ltok * DPd + idx];
        if (t < 64) { qs[t] = s;      g_q[l * Pp + t] = s; }
        else        { ks[t - 64] = s; g_k[l * Pp + (t - 64)] = s; }
        __syncthreads();
        float aq = b1[t], ak = 0.f;
        const float4* w4 = (const float4*)&W1[(size_t)t * DPd + Pp];
#pragma unroll
        for (int p4 = 0; p4 < 16; p4++) {
            float4 w = w4[p4];
            int b = p4 * 4;
            aq = fmaf(w.x, qs[b + 0], aq); ak = fmaf(w.x, ks[b + 0], ak);
            aq = fmaf(w.y, qs[b + 1], aq); ak = fmaf(w.y, ks[b + 1], ak);
            aq = fmaf(w.z, qs[b + 2], aq); ak = fmaf(w.z, ks[b + 2], ak);
            aq = fmaf(w.w, qs[b + 3], aq); ak = fmaf(w.w, ks[b + 3], ak);
        }
        g_Dq[l * Hd + t] = aq;
        g_Dk[l * Hd + t] = ak;
    } else if (blk < Ltok + 64) {
        int i = (blk - Ltok) * 128 + t;          // < 8192
        int h = i >> 6, p = i & 63;
        g_W1t[i] = __uint_as_float(f2tf(W1[(size_t)h * DPd + p]));
    } else if (blk < Ltok + 128) {
        int i = (blk - Ltok - 64) * 128 + t;     // i = n*128 + h
        g_W2gt[i] = __uint_as_float(f2tf(W2[i] * lng[i & 127]));
    } else {
        if (t < NBd) {
            float G = 0.f, C = 0.f;
            const float* wr = &W2[(size_t)t * Hd];
#pragma unroll 4
            for (int h = 0; h < Hd; h++) {
                float w = wr[h];
                G = fmaf(w, lng[h], G);
                C = fmaf(w, lnb[h], C);
            }
            g_Gvec[t] = G;
            g_Cvec[t] = C + b2[t];
        }
    }
}

// ===================== kernel 3: 1-term TF32 mma.sync fused main ==============
// CTA = 128 pairs (16 j x 8 i), 256 threads, 8 warps; warp w = i-row w, 16 pairs.
// out = rstd*(gelu(h) @ (g*W2)^T - mu*G) + C
// TF32 fragments loaded via ldmatrix.b16 on fp32-as-2-halves (see a0..a3 map).
// SMEM (bytes): 0 dq_s 16x132f (8448) | 8448 dk_s 8x132f (4224)
//   12672 Gs 256 | 12928 Cs 256
//   stage1: 14336 A1 32K (rows 256B) | 47104 B1 32K (rows 256B)
//   stage2: 14336 A2 64K (rows 512B, overlays A1+B1) | 79872 B2 32K (rows 512B)
//   total 112640 (2 CTAs/SM)
#define OFF_DQ   0
#define OFF_DK   8448
#define OFF_GS   12672
#define OFF_CS   12928
#define OFF_A1   14336
#define OFF_B1   47104
#define OFF_A2   14336
#define OFF_B2   79872
#define SMEM_MAIN 112640

__global__ __launch_bounds__(256, 2) void k_main(float* __restrict__ out) {
    extern __shared__ char smc[];
    const uint32_t sb = s2u(smc);
    const int t = threadIdx.x, wid = t >> 5, lid = t & 31;
    const int gid = lid >> 2, tig = lid & 3;
    const int j0 = blockIdx.x * 16;
    const int i0 = blockIdx.y * 8;

    float* dq_s = (float*)(smc + OFF_DQ);
    float* dk_s = (float*)(smc + OFF_DK);
    float* Gs   = (float*)(smc + OFF_GS);
    float* Cs   = (float*)(smc + OFF_CS);

    // ---- prologue fills ----
    // A1: hin = q*k (tf32-rounded fp32), rows 256B, swizzle chunk ^= row&7
    for (int idx = t; idx < 128 * 32; idx += 256) {
        int pair = idx >> 5, p = (idx & 31) * 2;
        int jj = pair & 15, ii = pair >> 4;
        float2 qv = *(const float2*)&g_q[(j0 + jj) * 64 + p];
        float2 kv = *(const float2*)&g_k[(i0 + ii) * 64 + p];
        uint2 v;
        v.x = f2tf(qv.x * kv.x);
        v.y = f2tf(qv.y * kv.y);
        uint32_t byte = (uint32_t)(pair * 256 + ((((p >> 2)) ^ (pair & 7)) << 4) + ((p & 3) << 2));
        *(uint2*)(smc + OFF_A1 + byte) = v;
    }
    // B1: W1t [h][p], rows 256B
    for (int idx = t; idx < 128 * 16; idx += 256) {
        int h = idx >> 4, c4 = idx & 15;
        uint32_t byte = (uint32_t)(h * 256 + ((c4 ^ (h & 7)) << 4));
        *(float4*)(smc + OFF_B1 + byte) = *(const float4*)&g_W1t[h * 64 + c4 * 4];
    }
    // B2: W2gt [n][h], rows 512B
    for (int idx = t; idx < 64 * 32; idx += 256) {
        int n = idx >> 5, c4 = idx & 31;
        uint32_t byte = (uint32_t)(n * 512 + ((c4 ^ (n & 7)) << 4));
        *(float4*)(smc + OFF_B2 + byte) = *(const float4*)&g_W2gt[n * 128 + c4 * 4];
    }
    for (int idx = t; idx < 16 * 32; idx += 256) {
        int jj = idx >> 5, c4 = idx & 31;
        *(float4*)&dq_s[jj * 132 + c4 * 4] = *(const float4*)&g_Dq[(j0 + jj) * 128 + c4 * 4];
    }
    for (int idx = t; idx < 8 * 32; idx += 256) {
        int ii = idx >> 5, c4 = idx & 31;
        *(float4*)&dk_s[ii * 132 + c4 * 4] = *(const float4*)&g_Dk[(i0 + ii) * 128 + c4 * 4];
    }
    if (t < 64)       Gs[t] = g_Gvec[t];
    else if (t < 128) Cs[t - 64] = g_Cvec[t - 64];
    __syncthreads();

    // ---- GEMM1: acc1[16 n-tiles][4], K=64 = 8 k8-steps, 1-term tf32 ----
    float acc1[16][4];
#pragma unroll
    for (int n = 0; n < 16; n++)
#pragma unroll
        for (int c = 0; c < 4; c++) acc1[n][c] = 0.f;

    const int pair0 = wid * 16;
#pragma unroll
    for (int ks = 0; ks < 8; ks++) {
        uint32_t a[4];
        {
            int row = pair0 + (lid & 15);
            int chunk = ks * 2 + (lid >> 4);
            uint32_t ad = sb + OFF_A1 + row * 256 + ((chunk ^ (row & 7)) << 4);
            LDSM4(a, ad);
        }
        int nro = (lid & 7) + ((lid >> 4) << 3);
        int bch = ks * 2 + ((lid >> 3) & 1);
#pragma unroll
        for (int np = 0; np < 8; np++) {
            int row = np * 16 + nro;
            uint32_t bd = sb + OFF_B1 + row * 256 + ((bch ^ (row & 7)) << 4);
            uint32_t b[4];
            LDSM4(b, bd);
            MMAT(acc1[2 * np],     a, b[0], b[1]);
            MMAT(acc1[2 * np + 1], a, b[2], b[3]);
        }
    }

    // ---- epilogue pass A: +Dq-Dk, exact GELU, row stats (4-lane shuffles) ----
    float mu[2], rs[2];
#pragma unroll
    for (int r = 0; r < 2; r++) {
        int prow = pair0 + gid + 8 * r;
        int jj = prow & 15;
        const float* dqr = &dq_s[jj * 132];
        const float* dkr = &dk_s[wid * 132];
        float s = 0.f, s2 = 0.f;
#pragma unroll
        for (int nt = 0; nt < 16; nt++) {
            int col = nt * 8 + tig * 2;
            float2 dq = *(const float2*)&dqr[col];
            float2 dk = *(const float2*)&dkr[col];
            float g0 = gelu_exact(acc1[nt][2 * r]     + dq.x - dk.x);
            float g1 = gelu_exact(acc1[nt][2 * r + 1] + dq.y - dk.y);
            s += g0 + g1; s2 += g0 * g0 + g1 * g1;
            acc1[nt][2 * r] = g0; acc1[nt][2 * r + 1] = g1;
        }
        s  += __shfl_xor_sync(0xffffffffu, s, 1);
        s  += __shfl_xor_sync(0xffffffffu, s, 2);
        s2 += __shfl_xor_sync(0xffffffffu, s2, 1);
        s2 += __shfl_xor_sync(0xffffffffu, s2, 2);
        mu[r] = s * (1.0f / 128.0f);
        float var = s2 * (1.0f / 128.0f) - mu[r] * mu[r];
        rs[r] = rsqrtf(var + 1e-5f);
    }
    __syncthreads();   // all warps done reading stage-1 tiles

    // ---- epilogue pass B: tf32-round gelu(h) -> A2 (rows 512B) ----
#pragma unroll
    for (int r = 0; r < 2; r++) {
        int prow = pair0 + gid + 8 * r;
        uint32_t rbase = (uint32_t)(prow * 512);
        uint32_t rx = (uint32_t)(prow & 7);
#pragma unroll
        for (int nt = 0; nt < 16; nt++) {
            uint2 v;
            v.x = f2tf(acc1[nt][2 * r]);
            v.y = f2tf(acc1[nt][2 * r + 1]);
            uint32_t chunk = (uint32_t)(nt * 2 + (tig >> 1));
            uint32_t byte = rbase + ((chunk ^ rx) << 4) + ((uint32_t)(tig & 1) << 3);
            *(uint2*)(smc + OFF_A2 + byte) = v;
        }
    }
    __syncthreads();

    // ---- GEMM2: acc2[8 n-tiles][4], K=128 = 16 k8-steps, 1-term tf32 ----
    float acc2[8][4];
#pragma unroll
    for (int n = 0; n < 8; n++)
#pragma unroll
        for (int c = 0; c < 4; c++) acc2[n][c] = 0.f;

#pragma unroll
    for (int ks = 0; ks < 16; ks++) {
        uint32_t a[4];
        {
            int row = pair0 + (lid & 15);
            int chunk = ks * 2 + (lid >> 4);
            uint32_t ad = sb + OFF_A2 + row * 512 + ((chunk ^ (row & 7)) << 4);
            LDSM4(a, ad);
        }
        int nro = (lid & 7) + ((lid >> 4) << 3);
        int bch = ks * 2 + ((lid >> 3) & 1);
#pragma unroll
        for (int np = 0; np < 4; np++) {
            int row = np * 16 + nro;
            uint32_t bd = sb + OFF_B2 + row * 512 + ((bch ^ (row & 7)) << 4);
            uint32_t b[4];
            LDSM4(b, bd);
            MMAT(acc2[2 * np],     a, b[0], b[1]);
            MMAT(acc2[2 * np + 1], a, b[2], b[3]);
        }
    }

    // ---- output: rstd*(acc2 - mu*G) + C ----
#pragma unroll
    for (int r = 0; r < 2; r++) {
        int prow = pair0 + gid + 8 * r;
        int jj = prow & 15;
        float* op = &out[((size_t)(i0 + wid) * Ltok + (j0 + jj)) * NBd];
#pragma unroll
        for (int nt = 0; nt < 8; nt++) {
            int col = nt * 8 + tig * 2;
            float2 G2 = *(const float2*)&Gs[col];
            float2 C2 = *(const float2*)&Cs[col];
            float2 o;
            o.x = rs[r] * (acc2[nt][2 * r]     - mu[r] * G2.x) + C2.x;
            o.y = rs[r] * (acc2[nt][2 * r + 1] - mu[r] * G2.y) + C2.y;
            *(float2*)&op[col] = o;
        }
    }
}

// =============================================================================
extern "C" void kernel_launch(void* const* d_in, const int* in_sizes, int n_in,
                              void* d_out, int out_size) {
    const float* x   = (const float*)d_in[0];
    const float* Wd  = (const float*)d_in[1];
    const float* bd  = (const float*)d_in[2];
    const float* W1  = (const float*)d_in[3];
    const float* b1  = (const float*)d_in[4];
    const float* lng = (const float*)d_in[5];
    const float* lnb = (const float*)d_in[6];
    const float* W2  = (const float*)d_in[7];
    const float* b2  = (const float*)d_in[8];
    float* out = (float*)d_out;

    cudaFuncSetAttribute(k_main, cudaFuncAttributeMaxDynamicSharedMemorySize, SMEM_MAIN);

    k_down<<<dim3(12, NKB), 256>>>(x, Wd);
    k_mid <<<Ltok + 129, 128>>>(bd, W1, b1, W2, lng, lnb, b2);
    k_main<<<dim3(48, 96), 256, SMEM_MAIN>>>(out);
}